// round 9
// baseline (speedup 1.0000x reference)
#include <cuda_runtime.h>
#include <math.h>

// Batched EKF, three independent 2x2 filters per segment (blocks
// {0,2},{1,3},{4,5}).  Block = 96 threads over 32 segments, ROLE WARPS:
// warp0 = filter A, warp1 = filter B, warp2 = filter C -- each warp carries
// only ~26 instr/step (balanced makespan; R8's AB warp carried 52 while its
// C warp idled).  768 warps = 130% SMSP coverage.  Measurements staged once
// per block into padded smem with coalesced float4 loads.  Diet Kalman
// algebra (w=iS*y, om=R*iS, Q folded into posterior).  Fused deterministic
// grid reduction (last-block pattern).

#define SEGS 32
#define THREADS 96

__device__ float g_partials[1024];
__device__ int   g_count = 0;

__device__ __forceinline__ float tanh_fast(float x){ float y; asm("tanh.approx.f32 %0, %1;" : "=f"(y) : "f"(x)); return y; }
__device__ __forceinline__ float rcp_fast (float x){ float y; asm("rcp.approx.f32 %0, %1;"  : "=f"(y) : "f"(x)); return y; }
__device__ __forceinline__ float lg2_fast (float x){ float y; asm("lg2.approx.f32 %0, %1;"  : "=f"(y) : "f"(x)); return y; }

__global__ void __launch_bounds__(THREADS) ekf_kernel(
    const float* __restrict__ params,
    const float* __restrict__ cp,
    const float* __restrict__ init_state,
    const float* __restrict__ meas,
    float* __restrict__ out,
    int N, int T)
{
    const float DT    = 1.0f / 120.0f;
    const float GRAV  = 9.81f;
    const float KS    = 100.0f;
    const float WRAP  = 4.71238898038469f;   // 1.5*pi
    const float TWOPI = 6.283185307179586f;
    const float LN2   = 0.6931471805599453f;

    const float fric = fabsf(params[0]);
    const float damp = fabsf(params[1]);
    const float fg    = fric * GRAV;
    const float cF    = 1.0f - DT * damp;
    const float nDTfg = -DT * fg;
    const float DTfgk = DT * fg * KS;
    const float cA    = cF - DTfgk;           // a = cA + DTfgk*th^2
    const float cF2   = cF * cF;

    extern __shared__ float sm[];             // [SEGS][3T+1] padded rows
    const int ROW = 3 * T + 1;                // 193 for T=64 -> conflict-free

    int tid  = threadIdx.x;
    int w    = tid >> 5;                      // 0=A, 1=B, 2=C (warp-uniform)
    int lane = tid & 31;
    int segBase = blockIdx.x * SEGS;

    // ---- cooperative coalesced staging ----
    {
        int valid = N - segBase;
        if (valid > SEGS) valid = SEGS;
        if (valid < 0) valid = 0;
        const float* gsrc = meas + (size_t)segBase * 3 * T;
        if (((3 * T) & 3) == 0) {
            int per = (3 * T) >> 2;                      // float4s per row
            int tot = valid * per;
            const float4* g4 = (const float4*)gsrc;
            for (int f = tid; f < tot; f += THREADS) {
                float4 v = g4[f];
                int seg = f / per;
                int off = (f - seg * per) << 2;
                float* d = sm + seg * ROW + off;
                d[0] = v.x; d[1] = v.y; d[2] = v.z; d[3] = v.w;
            }
        } else {
            int tot = valid * 3 * T;
            for (int f = tid; f < tot; f += THREADS) {
                int seg = f / (3 * T);
                int off = f - seg * 3 * T;
                sm[seg * ROW + off] = gsrc[f];
            }
        }
    }
    __syncthreads();

    int n = segBase + lane;
    float loss = 0.0f;

    if (n < N) {
        float acc_l2 = 0.0f, acc_m = 0.0f;

        if (w < 2) {
            // ============ A or B warp (nonlinear sub-filter) ============
            const float Rc = expf(cp[w]);          // R0 or R1
            const float Qp = expf(cp[3]);
            const float Qv = expf(cp[4]);

            float x = init_state[n*6 + w];         // state 0 or 1
            float v = init_state[n*6 + 2 + w];     // state 2 or 3
            float p00q = 0.01f + Qp, p01 = 0.0f, p11 = 0.01f;

            const float* zr = sm + lane * ROW + w; // z0 or z1 stream, stride 3

#define SUB(z_) do {                                                           \
            float th  = tanh_fast(KS * v);                                     \
            float xp  = fmaf(DT, v, x);                                        \
            float vp  = fmaf(cF, v, nDTfg * th);                               \
            float a   = fmaf(DTfgk, th * th, cA);                              \
            float m_  = fmaf(DT, p11, p01);                                    \
            float Pp01 = a * m_;                                               \
            float Pp00 = fmaf(DT, p01 + m_, p00q);                             \
            float Pp11 = fmaf(a * a, p11, Qv);                                 \
            float y  = (z_) - xp;                                              \
            float S  = Pp00 + Rc;                                              \
            float iS = rcp_fast(S);                                            \
            float w_ = iS * y;                                                 \
            x = fmaf(Pp00, w_, xp);                                            \
            v = fmaf(Pp01, w_, vp);                                            \
            float om = Rc * iS;                                                \
            p00q = fmaf(Pp00, om, Qp);                                         \
            p01  = Pp01 * om;                                                  \
            p11  = fmaf(-(Pp01 * iS), Pp01, Pp11);                             \
            acc_m = fmaf(y, w_, acc_m);                                        \
            sp *= S;                                                           \
        } while (0)

            if ((T & 3) == 0) {
                int G = T >> 2;
                for (int g = 0; g < G; g++) {
                    const float* zb = zr + g * 12;
                    float z0 = zb[0], z1 = zb[3], z2 = zb[6], z3 = zb[9];
                    float sp = 1.0f;
                    SUB(z0); SUB(z1); SUB(z2); SUB(z3);
                    acc_l2 += lg2_fast(sp);
                }
            } else {
                for (int t = 0; t < T; t++) {
                    float sp = 1.0f;
                    SUB(zr[t*3]);
                    acc_l2 += lg2_fast(sp);
                }
            }
#undef SUB
        } else {
            // ============ C warp (linear sub-filter, angle wrap) ============
            const float R2v = expf(cp[2]);
            const float Qt  = expf(cp[5]);
            const float Qo  = expf(cp[6]);

            float xC = init_state[n*6+4], vC = init_state[n*6+5];
            float pC00q = 0.01f + Qt, pC01 = 0.0f, pC11 = 0.01f;

            const float* zr = sm + lane * ROW + 2;

#define SUBC(z_) do {                                                          \
            float xp  = fmaf(DT, vC, xC);                                      \
            float vp  = cF * vC;                                               \
            float m_  = fmaf(DT, pC11, pC01);                                  \
            float Pp01 = cF * m_;                                              \
            float Pp00 = fmaf(DT, pC01 + m_, pC00q);                           \
            float Pp11 = fmaf(cF2, pC11, Qo);                                  \
            float y = (z_) - xp;                                               \
            if      (y >  WRAP) y -= TWOPI;                                    \
            else if (y < -WRAP) y += TWOPI;                                    \
            float S  = Pp00 + R2v;                                             \
            float iS = rcp_fast(S);                                            \
            float w_ = iS * y;                                                 \
            xC = fmaf(Pp00, w_, xp);                                           \
            vC = fmaf(Pp01, w_, vp);                                           \
            float om = R2v * iS;                                               \
            pC00q = fmaf(Pp00, om, Qt);                                        \
            pC01  = Pp01 * om;                                                 \
            pC11  = fmaf(-(Pp01 * iS), Pp01, Pp11);                            \
            acc_m = fmaf(y, w_, acc_m);                                        \
            sp *= S;                                                           \
        } while (0)

            if ((T & 3) == 0) {
                int G = T >> 2;
                for (int g = 0; g < G; g++) {
                    const float* zb = zr + g * 12;
                    float z0 = zb[0], z1 = zb[3], z2 = zb[6], z3 = zb[9];
                    float sp = 1.0f;
                    SUBC(z0); SUBC(z1); SUBC(z2); SUBC(z3);
                    acc_l2 += lg2_fast(sp);
                }
            } else {
                for (int t = 0; t < T; t++) {
                    float sp = 1.0f;
                    SUBC(zr[t*3]);
                    acc_l2 += lg2_fast(sp);
                }
            }
#undef SUBC
        }

        loss = 0.5f * fmaf(LN2, acc_l2, acc_m);
    }

    // ---- deterministic block reduction + last-block finish ----
    __shared__ float red[3];
    #pragma unroll
    for (int o = 16; o > 0; o >>= 1)
        loss += __shfl_down_sync(0xffffffffu, loss, o);
    if (lane == 0) red[w] = loss;
    __syncthreads();

    __shared__ int s_last;
    if (tid == 0) {
        g_partials[blockIdx.x] = red[0] + red[1] + red[2];
        __threadfence();
        int old = atomicAdd(&g_count, 1);
        s_last = (old == (int)gridDim.x - 1);
    }
    __syncthreads();
    if (s_last && w == 0) {
        __threadfence();
        int nb = gridDim.x;
        float acc = 0.0f;
        for (int j = lane; j < nb; j += 32)
            acc += g_partials[j];
        #pragma unroll
        for (int o = 16; o > 0; o >>= 1)
            acc += __shfl_down_sync(0xffffffffu, acc, o);
        if (lane == 0) {
            out[0] = acc / (float)N;
            g_count = 0;   // reset for next graph replay
        }
    }
}

extern "C" void kernel_launch(void* const* d_in, const int* in_sizes, int n_in,
                              void* d_out, int out_size)
{
    const float* params = (const float*)d_in[0];
    const float* cp     = (const float*)d_in[1];
    const float* x0     = (const float*)d_in[2];
    const float* meas   = (const float*)d_in[3];
    float* out = (float*)d_out;

    int N = in_sizes[2] / 6;
    int T = in_sizes[3] / (N * 3);
    int nblocks = (N + SEGS - 1) / SEGS;
    size_t smem = (size_t)SEGS * (3 * T + 1) * sizeof(float);

    ekf_kernel<<<nblocks, THREADS, smem>>>(params, cp, x0, meas, out, N, T);
}